// round 16
// baseline (speedup 1.0000x reference)
#include <cuda_runtime.h>
#include <cuda_bf16.h>
#include <math.h>

#define NN   50000
#define EE   400000
#define FINN 22
#define EDIM 22
#define D1   256
#define D2   512

#define W1COLS 1200    /* q(256)|k(256)|v(256)|skip(256)|qp(176) */
#define W2COLS 2304    /* q(512)|k(512)|v(512)|skip(512)|qp(176)|pad(80) */
#define W2VALID 2224

#define SCB  49

// ---------------- scratch ----------------------------------------------------
__device__ float g_y1[NN * W1COLS];
__device__ __nv_bfloat16 g_x1h[NN * D1];
__device__ float g_y2[NN * W2COLS];
__device__ __nv_bfloat16 g_kv1[NN * 2 * D1];
__device__ __nv_bfloat16 g_kv2[NN * 2 * D2];
__device__ __nv_bfloat16 g_wcat2h[W2COLS * D1];
__device__ __nv_bfloat16 g_attrp[EE * 24];   // attr permuted to CSR order, bf16
__device__ int   g_deg[NN];
__device__ int   g_cur[NN];
__device__ int   g_off[NN + 1];
__device__ int   g_csrc[EE];
__device__ int   g_ceid[EE];
__device__ float g_wcat1[FINN * W1COLS];
__device__ float g_bcat1[W1COLS];
__device__ float g_bcat2[W2COLS];
__device__ int   g_is64;
__device__ int   g_bsum[SCB];
__device__ int   g_bbase[SCB];

// ---------------- edge_index dtype detection --------------------------------
__global__ void k_detect(const int* __restrict__ ei) {
    int l = threadIdx.x;
    int nz = 0;
    for (int i = l; i < 1024; i += 32) nz |= (ei[2 * i + 1] != 0);
    unsigned m = __ballot_sync(0xffffffffu, nz);
    if (l == 0) g_is64 = (m == 0);
}
__device__ __forceinline__ int ld_src(const int* __restrict__ ei, int e) {
    return g_is64 ? ei[2 * e] : ei[e];
}
__device__ __forceinline__ int ld_dst(const int* __restrict__ ei, int e) {
    return g_is64 ? ei[2 * (EE + e)] : ei[EE + e];
}

// ---------------- CSR build ----------------
__global__ void k_zero_counters() {
    int i = blockIdx.x * blockDim.x + threadIdx.x;
    if (i < NN) { g_deg[i] = 0; g_cur[i] = 0; }
}
__global__ void k_hist(const int* __restrict__ ei) {
    int e = blockIdx.x * blockDim.x + threadIdx.x;
    if (e < EE) atomicAdd(&g_deg[ld_dst(ei, e)], 1);
}
__global__ void k_scan1() {
    __shared__ int sm[1024];
    int b = blockIdx.x;
    int i = b * 1024 + threadIdx.x;
    int v = (i < NN) ? g_deg[i] : 0;
    sm[threadIdx.x] = v;
    __syncthreads();
    for (int off = 1; off < 1024; off <<= 1) {
        int t = 0;
        if (threadIdx.x >= off) t = sm[threadIdx.x - off];
        __syncthreads();
        if (threadIdx.x >= off) sm[threadIdx.x] += t;
        __syncthreads();
    }
    if (i < NN) g_off[i + 1] = sm[threadIdx.x];
    if (threadIdx.x == 1023) g_bsum[b] = sm[1023];
}
__global__ void k_scan2() {
    if (threadIdx.x == 0) {
        int run = 0;
        for (int b = 0; b < SCB; b++) { g_bbase[b] = run; run += g_bsum[b]; }
        g_off[0] = 0;
    }
}
__global__ void k_scan3() {
    int i = blockIdx.x * blockDim.x + threadIdx.x;
    if (i < NN) g_off[i + 1] += g_bbase[i >> 10];
}
__global__ void k_scatter(const int* __restrict__ ei) {
    int e = blockIdx.x * blockDim.x + threadIdx.x;
    if (e < EE) {
        int src = ld_src(ei, e);
        int dst = ld_dst(ei, e);
        int pos = g_off[dst] + atomicAdd(&g_cur[dst], 1);
        g_csrc[pos] = src;
        g_ceid[pos] = e;
    }
}
// permute edge_attr into CSR position order (bf16, rows padded to 24)
__global__ void k_permattr(const float* __restrict__ attr) {
    int pos = blockIdx.x * blockDim.x + threadIdx.x;
    if (pos < EE) {
        int eid = g_ceid[pos];
        const float* ar = &attr[eid * EDIM];
        __nv_bfloat16* dp = &g_attrp[(size_t)pos * 24];
#pragma unroll
        for (int d = 0; d < EDIM; d++) dp[d] = __float2bfloat16_rn(ar[d]);
        dp[22] = __float2bfloat16_rn(0.f);
        dp[23] = __float2bfloat16_rn(0.f);
    }
}

// ---------------- weight concat builders -------------------------------------
__global__ void k_wcat1(const float* __restrict__ wq, const float* __restrict__ bq,
                        const float* __restrict__ wk, const float* __restrict__ bk,
                        const float* __restrict__ wv, const float* __restrict__ bv,
                        const float* __restrict__ we,
                        const float* __restrict__ ws, const float* __restrict__ bs) {
    int idx = blockIdx.x * blockDim.x + threadIdx.x;
    int wn = FINN * W1COLS;
    if (idx < wn) {
        int f = idx / W1COLS, c = idx % W1COLS;
        float val;
        if (c < 256)       val = wq[f * 256 + c];
        else if (c < 512)  val = wk[f * 256 + (c - 256)];
        else if (c < 768)  val = wv[f * 256 + (c - 512)];
        else if (c < 1024) val = ws[f * 256 + (c - 768)];
        else {
            int t = c - 1024, h = t / 22, g = t % 22;
            float s = 0.f;
            for (int cc = 0; cc < 32; cc++)
                s += wq[f * 256 + h * 32 + cc] * we[g * 256 + h * 32 + cc];
            val = s;
        }
        g_wcat1[f * W1COLS + c] = val;
    } else if (idx < wn + W1COLS) {
        int c = idx - wn;
        float val;
        if (c < 256)       val = bq[c];
        else if (c < 512)  val = bk[c - 256];
        else if (c < 768)  val = bv[c - 512];
        else if (c < 1024) val = bs[c - 768];
        else {
            int t = c - 1024, h = t / 22, g = t % 22;
            float s = 0.f;
            for (int cc = 0; cc < 32; cc++)
                s += bq[h * 32 + cc] * we[g * 256 + h * 32 + cc];
            val = s;
        }
        g_bcat1[c] = val;
    }
}

// layer2 weights: fold, convert to bf16, store TRANSPOSED [n=W2COLS][k=256]
__global__ void k_wcat2(const float* __restrict__ wq, const float* __restrict__ bq,
                        const float* __restrict__ wk, const float* __restrict__ bk,
                        const float* __restrict__ wv, const float* __restrict__ bv,
                        const float* __restrict__ we,
                        const float* __restrict__ ws, const float* __restrict__ bs) {
    int idx = blockIdx.x * blockDim.x + threadIdx.x;
    int wn = D1 * W2COLS;
    if (idx < wn) {
        int f = idx / W2COLS, c = idx % W2COLS;
        float val = 0.f;
        if (c < 512)        val = wq[f * 512 + c];
        else if (c < 1024)  val = wk[f * 512 + (c - 512)];
        else if (c < 1536)  val = wv[f * 512 + (c - 1024)];
        else if (c < 2048)  val = ws[f * 512 + (c - 1536)];
        else if (c < W2VALID) {
            int t = c - 2048, h = t / 22, g = t % 22;
            float s = 0.f;
            for (int cc = 0; cc < 64; cc++)
                s += wq[f * 512 + h * 64 + cc] * we[g * 512 + h * 64 + cc];
            val = s;
        }
        g_wcat2h[(size_t)c * D1 + f] = __float2bfloat16_rn(val);
    } else if (idx < wn + W2COLS) {
        int c = idx - wn;
        float val = 0.f;
        if (c < 512)        val = bq[c];
        else if (c < 1024)  val = bk[c - 512];
        else if (c < 1536)  val = bv[c - 1024];
        else if (c < 2048)  val = bs[c - 1536];
        else if (c < W2VALID) {
            int t = c - 2048, h = t / 22, g = t % 22;
            float s = 0.f;
            for (int cc = 0; cc < 64; cc++)
                s += bq[h * 64 + cc] * we[g * 512 + h * 64 + cc];
            val = s;
        }
        g_bcat2[c] = val;
    }
}

// ---------------- layer1 node GEMM -> g_y1 (+ bf16 k/v to g_kv1) -------------
__global__ void __launch_bounds__(256) k_gemm1(const float* __restrict__ x) {
    __shared__ float xs[FINN][128];
    __shared__ float ws[FINN][128];
    int m0 = blockIdx.x * 128;
    int c0 = blockIdx.y * 128;
    int t = threadIdx.x;
    for (int i = t; i < 128 * FINN; i += 256) {
        int n = i / FINN, f = i % FINN;
        xs[f][n] = (m0 + n < NN) ? x[(m0 + n) * FINN + f] : 0.f;
    }
    for (int i = t; i < FINN * 128; i += 256) {
        int f = i / 128, cc = i % 128;
        ws[f][cc] = (c0 + cc < W1COLS) ? g_wcat1[f * W1COLS + c0 + cc] : 0.f;
    }
    __syncthreads();
    int tr = t >> 4, tc = t & 15;
    float acc[8][8];
#pragma unroll
    for (int i = 0; i < 8; i++)
#pragma unroll
        for (int j = 0; j < 8; j++) acc[i][j] = 0.f;
#pragma unroll
    for (int f = 0; f < FINN; f++) {
        float a[8], b[8];
        *(float4*)(a)     = *(const float4*)&xs[f][tr * 8];
        *(float4*)(a + 4) = *(const float4*)&xs[f][tr * 8 + 4];
        *(float4*)(b)     = *(const float4*)&ws[f][tc * 8];
        *(float4*)(b + 4) = *(const float4*)&ws[f][tc * 8 + 4];
#pragma unroll
        for (int i = 0; i < 8; i++)
#pragma unroll
            for (int j = 0; j < 8; j++) acc[i][j] += a[i] * b[j];
    }
    int cb = c0 + tc * 8;
    float bb[8];
    if (cb + 7 < W1COLS) {
        *(float4*)(bb)     = *(const float4*)&g_bcat1[cb];
        *(float4*)(bb + 4) = *(const float4*)&g_bcat1[cb + 4];
        bool kv = (cb >= 256) && (cb < 768);
#pragma unroll
        for (int i = 0; i < 8; i++) {
            int row = m0 + tr * 8 + i;
            if (row >= NN) continue;
            float o[8];
#pragma unroll
            for (int jj = 0; jj < 8; jj++) o[jj] = acc[i][jj] + bb[jj];
            if (kv) {
                __nv_bfloat16 h[8];
#pragma unroll
                for (int jj = 0; jj < 8; jj++) h[jj] = __float2bfloat16_rn(o[jj]);
                *(uint4*)&g_kv1[row * (2 * D1) + (cb - 256)] = *(uint4*)h;
            } else {
                *(float4*)&g_y1[row * W1COLS + cb]     = *(float4*)(o);
                *(float4*)&g_y1[row * W1COLS + cb + 4] = *(float4*)(o + 4);
            }
        }
    }
}

// ---------------- layer2 GEMM: bf16 mma m16n8k16 + cp.async ------------------
__device__ __forceinline__ void mma_bf16(float* c, unsigned a0, unsigned a1,
                                         unsigned a2, unsigned a3,
                                         unsigned b0, unsigned b1) {
    asm volatile("mma.sync.aligned.m16n8k16.row.col.f32.bf16.bf16.f32 "
                 "{%0,%1,%2,%3}, {%4,%5,%6,%7}, {%8,%9}, {%0,%1,%2,%3};"
                 : "+f"(c[0]), "+f"(c[1]), "+f"(c[2]), "+f"(c[3])
                 : "r"(a0), "r"(a1), "r"(a2), "r"(a3), "r"(b0), "r"(b1));
}
__device__ __forceinline__ void cp16(void* sptr, const void* gptr) {
    unsigned sa = (unsigned)__cvta_generic_to_shared(sptr);
    asm volatile("cp.async.cg.shared.global [%0], [%1], 16;" :: "r"(sa), "l"(gptr));
}

#define HST 56
#define HTS (128 * HST)
#define G2_SMEM (4 * HTS * 2)

__global__ void __launch_bounds__(256) k_gemm2_tc() {
    extern __shared__ __nv_bfloat16 smh[];
    __nv_bfloat16* As[2] = { smh, smh + HTS };
    __nv_bfloat16* Bs[2] = { smh + 2 * HTS, smh + 3 * HTS };

    int m0 = blockIdx.x * 128;
    int c0 = blockIdx.y * 128;
    int t = threadIdx.x;
    int w = t >> 5, l = t & 31;
    int wm = (w >> 2) * 64;
    int wn = (w & 3) * 32;
    int gp = l >> 2, tq = l & 3;

    float acc[4][4][4];
#pragma unroll
    for (int a = 0; a < 4; a++)
#pragma unroll
        for (int b = 0; b < 4; b++)
#pragma unroll
            for (int cc = 0; cc < 4; cc++) acc[a][b][cc] = 0.f;

    auto load_stage = [&](int kc, int s) {
#pragma unroll
        for (int li = 0; li < 2; li++) {
            int idx = t + li * 256;
            int m = idx >> 2, chunk = (idx & 3) * 8;
            __nv_bfloat16* sp = &As[s][m * HST + chunk];
            if (m0 + m < NN)
                cp16(sp, &g_x1h[(m0 + m) * D1 + kc * 32 + chunk]);
            else {
                uint4 z = make_uint4(0, 0, 0, 0);
                *(uint4*)sp = z;
            }
        }
#pragma unroll
        for (int li = 0; li < 2; li++) {
            int idx = t + li * 256;
            int n = idx >> 2, chunk = (idx & 3) * 8;
            cp16(&Bs[s][n * HST + chunk],
                 &g_wcat2h[(size_t)(c0 + n) * D1 + kc * 32 + chunk]);
        }
    };

    load_stage(0, 0);
    asm volatile("cp.async.commit_group;");

    for (int kc = 0; kc < 8; kc++) {
        int cur = kc & 1;
        if (kc < 7) {
            load_stage(kc + 1, cur ^ 1);
            asm volatile("cp.async.commit_group;");
            asm volatile("cp.async.wait_group 1;");
        } else {
            asm volatile("cp.async.wait_group 0;");
        }
        __syncthreads();
        const __nv_bfloat16* A = As[cur];
        const __nv_bfloat16* B = Bs[cur];
#pragma unroll
        for (int kb = 0; kb < 2; kb++) {
            int k0 = kb * 16;
            unsigned af[4][4], bf[4][2];
#pragma unroll
            for (int mt = 0; mt < 4; mt++) {
                int row = wm + mt * 16 + gp;
                af[mt][0] = *(const unsigned*)&A[row * HST + k0 + 2 * tq];
                af[mt][1] = *(const unsigned*)&A[(row + 8) * HST + k0 + 2 * tq];
                af[mt][2] = *(const unsigned*)&A[row * HST + k0 + 2 * tq + 8];
                af[mt][3] = *(const unsigned*)&A[(row + 8) * HST + k0 + 2 * tq + 8];
            }
#pragma unroll
            for (int nt = 0; nt < 4; nt++) {
                int col = wn + nt * 8 + gp;
                bf[nt][0] = *(const unsigned*)&B[col * HST + k0 + 2 * tq];
                bf[nt][1] = *(const unsigned*)&B[col * HST + k0 + 2 * tq + 8];
            }
#pragma unroll
            for (int mt = 0; mt < 4; mt++)
#pragma unroll
                for (int nt = 0; nt < 4; nt++)
                    mma_bf16(acc[mt][nt], af[mt][0], af[mt][1], af[mt][2],
                             af[mt][3], bf[nt][0], bf[nt][1]);
        }
        __syncthreads();
    }
    bool kvblk = (c0 >= 512) && (c0 < 1536);
#pragma unroll
    for (int mt = 0; mt < 4; mt++) {
        int r0 = m0 + wm + mt * 16 + gp;
#pragma unroll
        for (int nt = 0; nt < 4; nt++) {
            int cb = c0 + wn + nt * 8 + tq * 2;
            float b0 = g_bcat2[cb], b1 = g_bcat2[cb + 1];
            if (kvblk) {
                if (r0 < NN) {
                    __nv_bfloat162 hv = __floats2bfloat162_rn(acc[mt][nt][0] + b0,
                                                              acc[mt][nt][1] + b1);
                    *(__nv_bfloat162*)&g_kv2[r0 * (2 * D2) + (cb - 512)] = hv;
                }
                if (r0 + 8 < NN) {
                    __nv_bfloat162 hv = __floats2bfloat162_rn(acc[mt][nt][2] + b0,
                                                              acc[mt][nt][3] + b1);
                    *(__nv_bfloat162*)&g_kv2[(r0 + 8) * (2 * D2) + (cb - 512)] = hv;
                }
            } else {
                if (r0 < NN)
                    *(float2*)&g_y2[r0 * W2COLS + cb] =
                        make_float2(acc[mt][nt][0] + b0, acc[mt][nt][1] + b1);
                if (r0 + 8 < NN)
                    *(float2*)&g_y2[(r0 + 8) * W2COLS + cb] =
                        make_float2(acc[mt][nt][2] + b0, acc[mt][nt][3] + b1);
            }
        }
    }
}

// ---------------- fused attention: flash-style, bf16 k/v + CSR-ordered attr --
template <int LAYER>
__global__ void __launch_bounds__(128) k_edge(const float* __restrict__ we,
                                              const float* __restrict__ wout,
                                              const float* __restrict__ bout,
                                              float* __restrict__ out) {
    constexpr int C   = (LAYER == 1) ? 32 : 64;
    constexpr int D   = 8 * C;
    constexpr int RS  = (LAYER == 1) ? W1COLS : W2COLS;
    constexpr int OS  = 3 * D;
    constexpr int OQP = 4 * D;
    constexpr int LPH = (LAYER == 1) ? 8 : 16;
    constexpr int NPB = (LAYER == 1) ? 2 : 1;
    constexpr int WPN = 4 / NPB;
    const float* ybuf = (LAYER == 1) ? g_y1 : g_y2;
    const __nv_bfloat16* kvbuf = (LAYER == 1) ? g_kv1 : g_kv2;
    const float scale = (LAYER == 1) ? 0.17677669529663687f : 0.125f;

    int w = threadIdx.x >> 5, l = threadIdx.x & 31;
    int node = w / WPN;
    int wl = w % WPN;
    int dst = blockIdx.x * NPB + node;
    int cbase = wl * 128;
    int h = (LAYER == 1) ? (wl * 4 + (l >> 3)) : (wl * 2 + (l >> 4));
    int j = l & (LPH - 1);
    int gb = l & ~(LPH - 1);

    int e0 = g_off[dst], deg = g_off[dst + 1] - e0;
    const float* drow = &ybuf[(size_t)dst * RS];

    float4 q4 = *(const float4*)&drow[cbase + 4 * l];
    const float* qp = &drow[OQP + h * 22];
    float qp0, qp1, qp2 = 0.f;
    if (LAYER == 1) {
        qp0 = qp[j]; qp1 = qp[8 + j]; qp2 = (j < 6) ? qp[16 + j] : 0.f;
    } else {
        qp0 = qp[j]; qp1 = (j < 6) ? qp[16 + j] : 0.f;
    }

    float m = -1e30f, s = 0.f;
    float4 acc = make_float4(0.f, 0.f, 0.f, 0.f);
    float aa0 = 0.f, aa1 = 0.f, aa2 = 0.f;

    auto body = [&](int pos, float& t, float4& v4, float& a0, float& a1, float& a2) {
        int srcn = __ldg(&g_csrc[pos]);
        const __nv_bfloat16* kvrow = &kvbuf[(size_t)srcn * (2 * D)];
        uint2 ku = __ldg((const uint2*)&kvrow[cbase + 4 * l]);
        uint2 vu = __ldg((const uint2*)&kvrow[D + cbase + 4 * l]);
        float2 k01 = __bfloat1622float2(*(__nv_bfloat162*)&ku.x);
        float2 k23 = __bfloat1622float2(*(__nv_bfloat162*)&ku.y);
        float2 w01 = __bfloat1622float2(*(__nv_bfloat162*)&vu.x);
        float2 w23 = __bfloat1622float2(*(__nv_bfloat162*)&vu.y);
        v4 = make_float4(w01.x, w01.y, w23.x, w23.y);
        const __nv_bfloat16* ar = &g_attrp[(size_t)pos * 24];
        if (LAYER == 1) {
            a0 = __bfloat162float(ar[j]);
            a1 = __bfloat162float(ar[8 + j]);
            a2 = (j < 6) ? __bfloat162float(ar[16 + j]) : 0.f;
            t = q4.x * k01.x + q4.y * k01.y + q4.z * k23.x + q4.w * k23.y
              + a0 * qp0 + a1 * qp1 + a2 * qp2;
        } else {
            a0 = __bfloat162float(ar[j]);
            a1 = (j < 6) ? __bfloat162float(ar[16 + j]) : 0.f;
            a2 = 0.f;
            t = q4.x * k01.x + q4.y * k01.y + q4.z * k23.x + q4.w * k23.y
              + a0 * qp0 + a1 * qp1;
        }
#pragma unroll
        for (int o = LPH / 2; o; o >>= 1)
            t += __shfl_xor_sync(0xffffffffu, t, o);
        t *= scale;
    };

    int i = 0;
    for (; i + 2 <= deg; i += 2) {
        float t0, t1;
        float4 v0, v1;
        float a00, a01, a02, a10, a11, a12;
        body(e0 + i,     t0, v0, a00, a01, a02);
        body(e0 + i + 1, t1, v1, a10, a11, a12);
        float nm = fmaxf(m, fmaxf(t0, t1));
        float c  = __expf(m - nm);
        float p0 = __expf(t0 - nm);
        float p1 = __expf(t1 - nm);
        s = s * c + p0 + p1;
        acc.x = acc.x * c + p0 * v0.x + p1 * v1.x;
        acc.y = acc.y * c + p0 * v0.y + p1 * v1.y;
        acc.z = acc.z * c + p0 * v0.z + p1 * v1.z;
        acc.w = acc.w * c + p0 * v0.w + p1 * v1.w;
        aa0 = aa0 * c + p0 * a00 + p1 * a10;
        aa1 = aa1 * c + p0 * a01 + p1 * a11;
        if (LAYER == 1) aa2 = aa2 * c + p0 * a02 + p1 * a12;
        m = nm;
    }
    if (i < deg) {
        float t0;
        float4 v0;
        float a00, a01, a02;
        body(e0 + i, t0, v0, a00, a01, a02);
        float nm = fmaxf(m, t0);
        float c  = __expf(m - nm);
        float p0 = __expf(t0 - nm);
        s = s * c + p0;
        acc.x = acc.x * c + p0 * v0.x;
        acc.y = acc.y * c + p0 * v0.y;
        acc.z = acc.z * c + p0 * v0.z;
        acc.w = acc.w * c + p0 * v0.w;
        aa0 = aa0 * c + p0 * a00;
        aa1 = aa1 * c + p0 * a01;
        if (LAYER == 1) aa2 = aa2 * c + p0 * a02;
        m = nm;
    }

    float inv = 1.f / (s + 1e-16f);
    acc.x *= inv; acc.y *= inv; acc.z *= inv; acc.w *= inv;
    aa0 *= inv; aa1 *= inv; aa2 *= inv;

    // attr-message: out_h += (sum_e alpha_eh * attr_e) @ We_h
    float4 ex = make_float4(0.f, 0.f, 0.f, 0.f);
#pragma unroll
    for (int g = 0; g < 22; g++) {
        float aag;
        if (g < LPH)            aag = __shfl_sync(0xffffffffu, aa0, gb + g);
        else if (g < 2 * LPH)   aag = __shfl_sync(0xffffffffu, aa1, gb + g - LPH);
        else                    aag = __shfl_sync(0xffffffffu, aa2, gb + g - 2 * LPH);
        float4 w4 = __ldg((const float4*)&we[g * D + cbase + 4 * l]);
        ex.x += aag * w4.x; ex.y += aag * w4.y;
        ex.z += aag * w4.z; ex.w += aag * w4.w;
    }

    float4 sk = *(const float4*)&drow[OS + cbase + 4 * l];
    float4 o;
    o.x = fmaxf(sk.x + acc.x + ex.x, 0.f);
    o.y = fmaxf(sk.y + acc.y + ex.y, 0.f);
    o.z = fmaxf(sk.z + acc.z + ex.z, 0.f);
    o.w = fmaxf(sk.w + acc.w + ex.w, 0.f);

    if (LAYER == 1) {
        __nv_bfloat16 hh[4];
        hh[0] = __float2bfloat16_rn(o.x);
        hh[1] = __float2bfloat16_rn(o.y);
        hh[2] = __float2bfloat16_rn(o.z);
        hh[3] = __float2bfloat16_rn(o.w);
        *(uint2*)&g_x1h[dst * D1 + cbase + 4 * l] = *(uint2*)hh;
    } else {
        // fused output head: sigmoid([x1 | x2] @ w_out + b)
        int c2 = cbase + 4 * l;
        float4 w4 = __ldg((const float4*)&wout[D1 + c2]);
        float part = o.x * w4.x + o.y * w4.y + o.z * w4.z + o.w * w4.w;
        int c1 = threadIdx.x * 2;
        __nv_bfloat162 x1h = *(const __nv_bfloat162*)&g_x1h[dst * D1 + c1];
        float2 x1v = __bfloat1622float2(x1h);
        float2 w1v = __ldg((const float2*)&wout[c1]);
        part += x1v.x * w1v.x + x1v.y * w1v.y;
#pragma unroll
        for (int of = 16; of; of >>= 1)
            part += __shfl_xor_sync(0xffffffffu, part, of);
        __shared__ float wsum[4];
        if (l == 0) wsum[w] = part;
        __syncthreads();
        if (threadIdx.x == 0) {
            float sfull = wsum[0] + wsum[1] + wsum[2] + wsum[3] + bout[0];
            out[dst] = 1.f / (1.f + expf(-sfull));
        }
    }
}

// ---------------- launch (forked-stream capture for DAG overlap) -------------
extern "C" void kernel_launch(void* const* d_in, const int* in_sizes, int n_in,
                              void* d_out, int out_size) {
    const float* x  = (const float*)d_in[0];
    const int*   ei = (const int*)d_in[1];
    const float* ea = (const float*)d_in[2];
    const float* w1_q = (const float*)d_in[3];  const float* b1_q = (const float*)d_in[4];
    const float* w1_k = (const float*)d_in[5];  const float* b1_k = (const float*)d_in[6];
    const float* w1_v = (const float*)d_in[7];  const float* b1_v = (const float*)d_in[8];
    const float* w1_e = (const float*)d_in[9];
    const float* w1_s = (const float*)d_in[10]; const float* b1_s = (const float*)d_in[11];
    const float* w2_q = (const float*)d_in[12]; const float* b2_q = (const float*)d_in[13];
    const float* w2_k = (const float*)d_in[14]; const float* b2_k = (const float*)d_in[15];
    const float* w2_v = (const float*)d_in[16]; const float* b2_v = (const float*)d_in[17];
    const float* w2_e = (const float*)d_in[18];
    const float* w2_s = (const float*)d_in[19]; const float* b2_s = (const float*)d_in[20];
    const float* w_out = (const float*)d_in[21];
    const float* b_out = (const float*)d_in[22];
    float* out = (float*)d_out;

    static int inited = 0;
    static cudaStream_t sA, sB;
    static cudaEvent_t evRoot, evA, evB;
    if (!inited) {
        cudaFuncSetAttribute(k_gemm2_tc,
                             cudaFuncAttributeMaxDynamicSharedMemorySize, G2_SMEM);
        cudaStreamCreateWithFlags(&sA, cudaStreamNonBlocking);
        cudaStreamCreateWithFlags(&sB, cudaStreamNonBlocking);
        cudaEventCreateWithFlags(&evRoot, cudaEventDisableTiming);
        cudaEventCreateWithFlags(&evA, cudaEventDisableTiming);
        cudaEventCreateWithFlags(&evB, cudaEventDisableTiming);
        inited = 1;
    }

    // fork side streams off the capture-origin stream
    cudaEventRecord(evRoot, 0);
    cudaStreamWaitEvent(sA, evRoot, 0);
    cudaStreamWaitEvent(sB, evRoot, 0);

    // stream A: CSR build + attr permute (independent of GEMMs)
    k_detect<<<1, 32, 0, sA>>>(ei);
    k_zero_counters<<<(NN + 255) / 256, 256, 0, sA>>>();
    k_hist<<<(EE + 255) / 256, 256, 0, sA>>>(ei);
    k_scan1<<<SCB, 1024, 0, sA>>>();
    k_scan2<<<1, 64, 0, sA>>>();
    k_scan3<<<(NN + 255) / 256, 256, 0, sA>>>();
    k_scatter<<<(EE + 255) / 256, 256, 0, sA>>>(ei);
    k_permattr<<<(EE + 255) / 256, 256, 0, sA>>>(ea);
    cudaEventRecord(evA, sA);

    // stream B: layer2 weight fold (needed only by gemm2)
    k_wcat2<<<(D1 * W2COLS + W2COLS + 255) / 256, 256, 0, sB>>>(
        w2_q, b2_q, w2_k, b2_k, w2_v, b2_v, w2_e, w2_s, b2_s);
    cudaEventRecord(evB, sB);

    // main stream: layer1 projection
    k_wcat1<<<(FINN * W1COLS + W1COLS + 255) / 256, 256>>>(w1_q, b1_q, w1_k, b1_k,
                                                           w1_v, b1_v, w1_e, w1_s, b1_s);
    {
        dim3 g((NN + 127) / 128, (W1COLS + 127) / 128);
        k_gemm1<<<g, 256>>>(x);
    }
    cudaStreamWaitEvent(0, evA, 0);      // join CSR+permattr before edge pass
    k_edge<1><<<NN / 2, 128>>>(w1_e, w_out, b_out, out);

    cudaStreamWaitEvent(0, evB, 0);      // join wcat2 before gemm2
    {
        dim3 g((NN + 127) / 128, W2COLS / 128);
        k_gemm2_tc<<<g, 256, G2_SMEM>>>();
    }
    k_edge<2><<<NN, 128>>>(w2_e, w_out, b_out, out);
}

// round 17
// speedup vs baseline: 1.0509x; 1.0509x over previous
#include <cuda_runtime.h>
#include <cuda_bf16.h>
#include <math.h>

#define NN   50000
#define EE   400000
#define FINN 22
#define EDIM 22
#define D1   256
#define D2   512

#define W1COLS 1200    /* q(256)|k(256)|v(256)|skip(256)|qp(176) */
#define W2COLS 2304    /* q(512)|k(512)|v(512)|skip(512)|qp(176)|pad(80) */
#define W2VALID 2224

#define SCB  49

// ---------------- scratch ----------------------------------------------------
__device__ float g_y1[NN * W1COLS];
__device__ __nv_bfloat16 g_x1h[NN * D1];
__device__ float g_y2[NN * W2COLS];
__device__ __nv_bfloat16 g_kv1[NN * 2 * D1];
__device__ __nv_bfloat16 g_kv2[NN * 2 * D2];
__device__ __nv_bfloat16 g_wcat2h[W2COLS * D1];
__device__ int   g_deg[NN];
__device__ int   g_cur[NN];
__device__ int   g_off[NN + 1];
__device__ int2  g_eidx[EE];
__device__ float g_wcat1[FINN * W1COLS];
__device__ float g_bcat1[W1COLS];
__device__ float g_bcat2[W2COLS];
__device__ int   g_is64;
__device__ int   g_bsum[SCB];
__device__ int   g_bbase[SCB];

// ---------------- edge_index dtype detection --------------------------------
__global__ void k_detect(const int* __restrict__ ei) {
    int l = threadIdx.x;
    int nz = 0;
    for (int i = l; i < 1024; i += 32) nz |= (ei[2 * i + 1] != 0);
    unsigned m = __ballot_sync(0xffffffffu, nz);
    if (l == 0) g_is64 = (m == 0);
}
__device__ __forceinline__ int ld_src(const int* __restrict__ ei, int e) {
    return g_is64 ? ei[2 * e] : ei[e];
}
__device__ __forceinline__ int ld_dst(const int* __restrict__ ei, int e) {
    return g_is64 ? ei[2 * (EE + e)] : ei[EE + e];
}

// ---------------- CSR build ----------------
__global__ void k_zero_counters() {
    int i = blockIdx.x * blockDim.x + threadIdx.x;
    if (i < NN) { g_deg[i] = 0; g_cur[i] = 0; }
}
__global__ void k_hist(const int* __restrict__ ei) {
    int e = blockIdx.x * blockDim.x + threadIdx.x;
    if (e < EE) atomicAdd(&g_deg[ld_dst(ei, e)], 1);
}
__global__ void k_scan1() {
    __shared__ int sm[1024];
    int b = blockIdx.x;
    int i = b * 1024 + threadIdx.x;
    int v = (i < NN) ? g_deg[i] : 0;
    sm[threadIdx.x] = v;
    __syncthreads();
    for (int off = 1; off < 1024; off <<= 1) {
        int t = 0;
        if (threadIdx.x >= off) t = sm[threadIdx.x - off];
        __syncthreads();
        if (threadIdx.x >= off) sm[threadIdx.x] += t;
        __syncthreads();
    }
    if (i < NN) g_off[i + 1] = sm[threadIdx.x];
    if (threadIdx.x == 1023) g_bsum[b] = sm[1023];
}
__global__ void k_scan2() {
    if (threadIdx.x == 0) {
        int run = 0;
        for (int b = 0; b < SCB; b++) { g_bbase[b] = run; run += g_bsum[b]; }
        g_off[0] = 0;
    }
}
__global__ void k_scan3() {
    int i = blockIdx.x * blockDim.x + threadIdx.x;
    if (i < NN) g_off[i + 1] += g_bbase[i >> 10];
}
__global__ void k_scatter(const int* __restrict__ ei) {
    int e = blockIdx.x * blockDim.x + threadIdx.x;
    if (e < EE) {
        int src = ld_src(ei, e);
        int dst = ld_dst(ei, e);
        int pos = g_off[dst] + atomicAdd(&g_cur[dst], 1);
        g_eidx[pos] = make_int2(src, e);
    }
}

// ---------------- weight concat builders -------------------------------------
__global__ void k_wcat1(const float* __restrict__ wq, const float* __restrict__ bq,
                        const float* __restrict__ wk, const float* __restrict__ bk,
                        const float* __restrict__ wv, const float* __restrict__ bv,
                        const float* __restrict__ we,
                        const float* __restrict__ ws, const float* __restrict__ bs) {
    int idx = blockIdx.x * blockDim.x + threadIdx.x;
    int wn = FINN * W1COLS;
    if (idx < wn) {
        int f = idx / W1COLS, c = idx % W1COLS;
        float val;
        if (c < 256)       val = wq[f * 256 + c];
        else if (c < 512)  val = wk[f * 256 + (c - 256)];
        else if (c < 768)  val = wv[f * 256 + (c - 512)];
        else if (c < 1024) val = ws[f * 256 + (c - 768)];
        else {
            int t = c - 1024, h = t / 22, g = t % 22;
            float s = 0.f;
            for (int cc = 0; cc < 32; cc++)
                s += wq[f * 256 + h * 32 + cc] * we[g * 256 + h * 32 + cc];
            val = s;
        }
        g_wcat1[f * W1COLS + c] = val;
    } else if (idx < wn + W1COLS) {
        int c = idx - wn;
        float val;
        if (c < 256)       val = bq[c];
        else if (c < 512)  val = bk[c - 256];
        else if (c < 768)  val = bv[c - 512];
        else if (c < 1024) val = bs[c - 768];
        else {
            int t = c - 1024, h = t / 22, g = t % 22;
            float s = 0.f;
            for (int cc = 0; cc < 32; cc++)
                s += bq[h * 32 + cc] * we[g * 256 + h * 32 + cc];
            val = s;
        }
        g_bcat1[c] = val;
    }
}

// layer2 weights: fold, convert to bf16, store TRANSPOSED [n=W2COLS][k=256]
__global__ void k_wcat2(const float* __restrict__ wq, const float* __restrict__ bq,
                        const float* __restrict__ wk, const float* __restrict__ bk,
                        const float* __restrict__ wv, const float* __restrict__ bv,
                        const float* __restrict__ we,
                        const float* __restrict__ ws, const float* __restrict__ bs) {
    int idx = blockIdx.x * blockDim.x + threadIdx.x;
    int wn = D1 * W2COLS;
    if (idx < wn) {
        int f = idx / W2COLS, c = idx % W2COLS;
        float val = 0.f;
        if (c < 512)        val = wq[f * 512 + c];
        else if (c < 1024)  val = wk[f * 512 + (c - 512)];
        else if (c < 1536)  val = wv[f * 512 + (c - 1024)];
        else if (c < 2048)  val = ws[f * 512 + (c - 1536)];
        else if (c < W2VALID) {
            int t = c - 2048, h = t / 22, g = t % 22;
            float s = 0.f;
            for (int cc = 0; cc < 64; cc++)
                s += wq[f * 512 + h * 64 + cc] * we[g * 512 + h * 64 + cc];
            val = s;
        }
        g_wcat2h[(size_t)c * D1 + f] = __float2bfloat16_rn(val);
    } else if (idx < wn + W2COLS) {
        int c = idx - wn;
        float val = 0.f;
        if (c < 512)        val = bq[c];
        else if (c < 1024)  val = bk[c - 512];
        else if (c < 1536)  val = bv[c - 1024];
        else if (c < 2048)  val = bs[c - 1536];
        else if (c < W2VALID) {
            int t = c - 2048, h = t / 22, g = t % 22;
            float s = 0.f;
            for (int cc = 0; cc < 64; cc++)
                s += bq[h * 64 + cc] * we[g * 512 + h * 64 + cc];
            val = s;
        }
        g_bcat2[c] = val;
    }
}

// ---------------- layer1 node GEMM -> g_y1 (+ bf16 k/v to g_kv1) -------------
__global__ void __launch_bounds__(256) k_gemm1(const float* __restrict__ x) {
    __shared__ float xs[FINN][128];
    __shared__ float ws[FINN][128];
    int m0 = blockIdx.x * 128;
    int c0 = blockIdx.y * 128;
    int t = threadIdx.x;
    for (int i = t; i < 128 * FINN; i += 256) {
        int n = i / FINN, f = i % FINN;
        xs[f][n] = (m0 + n < NN) ? x[(m0 + n) * FINN + f] : 0.f;
    }
    for (int i = t; i < FINN * 128; i += 256) {
        int f = i / 128, cc = i % 128;
        ws[f][cc] = (c0 + cc < W1COLS) ? g_wcat1[f * W1COLS + c0 + cc] : 0.f;
    }
    __syncthreads();
    int tr = t >> 4, tc = t & 15;
    float acc[8][8];
#pragma unroll
    for (int i = 0; i < 8; i++)
#pragma unroll
        for (int j = 0; j < 8; j++) acc[i][j] = 0.f;
#pragma unroll
    for (int f = 0; f < FINN; f++) {
        float a[8], b[8];
        *(float4*)(a)     = *(const float4*)&xs[f][tr * 8];
        *(float4*)(a + 4) = *(const float4*)&xs[f][tr * 8 + 4];
        *(float4*)(b)     = *(const float4*)&ws[f][tc * 8];
        *(float4*)(b + 4) = *(const float4*)&ws[f][tc * 8 + 4];
#pragma unroll
        for (int i = 0; i < 8; i++)
#pragma unroll
            for (int j = 0; j < 8; j++) acc[i][j] += a[i] * b[j];
    }
    int cb = c0 + tc * 8;
    float bb[8];
    if (cb + 7 < W1COLS) {
        *(float4*)(bb)     = *(const float4*)&g_bcat1[cb];
        *(float4*)(bb + 4) = *(const float4*)&g_bcat1[cb + 4];
        bool kv = (cb >= 256) && (cb < 768);
#pragma unroll
        for (int i = 0; i < 8; i++) {
            int row = m0 + tr * 8 + i;
            if (row >= NN) continue;
            float o[8];
#pragma unroll
            for (int jj = 0; jj < 8; jj++) o[jj] = acc[i][jj] + bb[jj];
            if (kv) {
                __nv_bfloat16 h[8];
#pragma unroll
                for (int jj = 0; jj < 8; jj++) h[jj] = __float2bfloat16_rn(o[jj]);
                *(uint4*)&g_kv1[row * (2 * D1) + (cb - 256)] = *(uint4*)h;
            } else {
                *(float4*)&g_y1[row * W1COLS + cb]     = *(float4*)(o);
                *(float4*)&g_y1[row * W1COLS + cb + 4] = *(float4*)(o + 4);
            }
        }
    }
}

// ---------------- layer2 GEMM: bf16 mma m16n8k16 + cp.async ------------------
__device__ __forceinline__ void mma_bf16(float* c, unsigned a0, unsigned a1,
                                         unsigned a2, unsigned a3,
                                         unsigned b0, unsigned b1) {
    asm volatile("mma.sync.aligned.m16n8k16.row.col.f32.bf16.bf16.f32 "
                 "{%0,%1,%2,%3}, {%4,%5,%6,%7}, {%8,%9}, {%0,%1,%2,%3};"
                 : "+f"(c[0]), "+f"(c[1]), "+f"(c[2]), "+f"(c[3])
                 : "r"(a0), "r"(a1), "r"(a2), "r"(a3), "r"(b0), "r"(b1));
}
__device__ __forceinline__ void cp16(void* sptr, const void* gptr) {
    unsigned sa = (unsigned)__cvta_generic_to_shared(sptr);
    asm volatile("cp.async.cg.shared.global [%0], [%1], 16;" :: "r"(sa), "l"(gptr));
}

#define HST 56
#define HTS (128 * HST)
#define G2_SMEM (4 * HTS * 2)

__global__ void __launch_bounds__(256) k_gemm2_tc() {
    extern __shared__ __nv_bfloat16 smh[];
    __nv_bfloat16* As[2] = { smh, smh + HTS };
    __nv_bfloat16* Bs[2] = { smh + 2 * HTS, smh + 3 * HTS };

    int m0 = blockIdx.x * 128;
    int c0 = blockIdx.y * 128;
    int t = threadIdx.x;
    int w = t >> 5, l = t & 31;
    int wm = (w >> 2) * 64;
    int wn = (w & 3) * 32;
    int gp = l >> 2, tq = l & 3;

    float acc[4][4][4];
#pragma unroll
    for (int a = 0; a < 4; a++)
#pragma unroll
        for (int b = 0; b < 4; b++)
#pragma unroll
            for (int cc = 0; cc < 4; cc++) acc[a][b][cc] = 0.f;

    auto load_stage = [&](int kc, int s) {
#pragma unroll
        for (int li = 0; li < 2; li++) {
            int idx = t + li * 256;
            int m = idx >> 2, chunk = (idx & 3) * 8;
            __nv_bfloat16* sp = &As[s][m * HST + chunk];
            if (m0 + m < NN)
                cp16(sp, &g_x1h[(m0 + m) * D1 + kc * 32 + chunk]);
            else {
                uint4 z = make_uint4(0, 0, 0, 0);
                *(uint4*)sp = z;
            }
        }
#pragma unroll
        for (int li = 0; li < 2; li++) {
            int idx = t + li * 256;
            int n = idx >> 2, chunk = (idx & 3) * 8;
            cp16(&Bs[s][n * HST + chunk],
                 &g_wcat2h[(size_t)(c0 + n) * D1 + kc * 32 + chunk]);
        }
    };

    load_stage(0, 0);
    asm volatile("cp.async.commit_group;");

    for (int kc = 0; kc < 8; kc++) {
        int cur = kc & 1;
        if (kc < 7) {
            load_stage(kc + 1, cur ^ 1);
            asm volatile("cp.async.commit_group;");
            asm volatile("cp.async.wait_group 1;");
        } else {
            asm volatile("cp.async.wait_group 0;");
        }
        __syncthreads();
        const __nv_bfloat16* A = As[cur];
        const __nv_bfloat16* B = Bs[cur];
#pragma unroll
        for (int kb = 0; kb < 2; kb++) {
            int k0 = kb * 16;
            unsigned af[4][4], bf[4][2];
#pragma unroll
            for (int mt = 0; mt < 4; mt++) {
                int row = wm + mt * 16 + gp;
                af[mt][0] = *(const unsigned*)&A[row * HST + k0 + 2 * tq];
                af[mt][1] = *(const unsigned*)&A[(row + 8) * HST + k0 + 2 * tq];
                af[mt][2] = *(const unsigned*)&A[row * HST + k0 + 2 * tq + 8];
                af[mt][3] = *(const unsigned*)&A[(row + 8) * HST + k0 + 2 * tq + 8];
            }
#pragma unroll
            for (int nt = 0; nt < 4; nt++) {
                int col = wn + nt * 8 + gp;
                bf[nt][0] = *(const unsigned*)&B[col * HST + k0 + 2 * tq];
                bf[nt][1] = *(const unsigned*)&B[col * HST + k0 + 2 * tq + 8];
            }
#pragma unroll
            for (int mt = 0; mt < 4; mt++)
#pragma unroll
                for (int nt = 0; nt < 4; nt++)
                    mma_bf16(acc[mt][nt], af[mt][0], af[mt][1], af[mt][2],
                             af[mt][3], bf[nt][0], bf[nt][1]);
        }
        __syncthreads();
    }
    bool kvblk = (c0 >= 512) && (c0 < 1536);
#pragma unroll
    for (int mt = 0; mt < 4; mt++) {
        int r0 = m0 + wm + mt * 16 + gp;
#pragma unroll
        for (int nt = 0; nt < 4; nt++) {
            int cb = c0 + wn + nt * 8 + tq * 2;
            float b0 = g_bcat2[cb], b1 = g_bcat2[cb + 1];
            if (kvblk) {
                if (r0 < NN) {
                    __nv_bfloat162 hv = __floats2bfloat162_rn(acc[mt][nt][0] + b0,
                                                              acc[mt][nt][1] + b1);
                    *(__nv_bfloat162*)&g_kv2[r0 * (2 * D2) + (cb - 512)] = hv;
                }
                if (r0 + 8 < NN) {
                    __nv_bfloat162 hv = __floats2bfloat162_rn(acc[mt][nt][2] + b0,
                                                              acc[mt][nt][3] + b1);
                    *(__nv_bfloat162*)&g_kv2[(r0 + 8) * (2 * D2) + (cb - 512)] = hv;
                }
            } else {
                if (r0 < NN)
                    *(float2*)&g_y2[r0 * W2COLS + cb] =
                        make_float2(acc[mt][nt][0] + b0, acc[mt][nt][1] + b1);
                if (r0 + 8 < NN)
                    *(float2*)&g_y2[(r0 + 8) * W2COLS + cb] =
                        make_float2(acc[mt][nt][2] + b0, acc[mt][nt][3] + b1);
            }
        }
    }
}

// ---------------- fused attention: flash-style, bf16 k/v, 4x edge unroll -----
// LAYER==2 also fuses the output head.
template <int LAYER>
__global__ void __launch_bounds__(128) k_edge(const float* __restrict__ attr,
                                              const float* __restrict__ we,
                                              const float* __restrict__ wout,
                                              const float* __restrict__ bout,
                                              float* __restrict__ out) {
    constexpr int C   = (LAYER == 1) ? 32 : 64;
    constexpr int D   = 8 * C;
    constexpr int RS  = (LAYER == 1) ? W1COLS : W2COLS;
    constexpr int OS  = 3 * D;
    constexpr int OQP = 4 * D;
    constexpr int LPH = (LAYER == 1) ? 8 : 16;
    constexpr int NPB = (LAYER == 1) ? 2 : 1;
    constexpr int WPN = 4 / NPB;
    const float* ybuf = (LAYER == 1) ? g_y1 : g_y2;
    const __nv_bfloat16* kvbuf = (LAYER == 1) ? g_kv1 : g_kv2;
    const float scale = (LAYER == 1) ? 0.17677669529663687f : 0.125f;

    int w = threadIdx.x >> 5, l = threadIdx.x & 31;
    int node = w / WPN;
    int wl = w % WPN;
    int dst = blockIdx.x * NPB + node;
    int cbase = wl * 128;
    int h = (LAYER == 1) ? (wl * 4 + (l >> 3)) : (wl * 2 + (l >> 4));
    int j = l & (LPH - 1);
    int gb = l & ~(LPH - 1);

    int e0 = g_off[dst], deg = g_off[dst + 1] - e0;
    const float* drow = &ybuf[(size_t)dst * RS];

    float4 q4 = *(const float4*)&drow[cbase + 4 * l];
    const float* qp = &drow[OQP + h * 22];
    float qp0, qp1, qp2 = 0.f;
    if (LAYER == 1) {
        qp0 = qp[j]; qp1 = qp[8 + j]; qp2 = (j < 6) ? qp[16 + j] : 0.f;
    } else {
        qp0 = qp[j]; qp1 = (j < 6) ? qp[16 + j] : 0.f;
    }

    float m = -1e30f, s = 0.f;
    float4 acc = make_float4(0.f, 0.f, 0.f, 0.f);
    float aa0 = 0.f, aa1 = 0.f, aa2 = 0.f;

    auto body = [&](int pos, float& t, float4& v4, float& a0, float& a1, float& a2) {
        int2 se = __ldg(&g_eidx[pos]);
        int srcn = se.x, eid = se.y;
        const __nv_bfloat16* kvrow = &kvbuf[(size_t)srcn * (2 * D)];
        uint2 ku = __ldg((const uint2*)&kvrow[cbase + 4 * l]);
        uint2 vu = __ldg((const uint2*)&kvrow[D + cbase + 4 * l]);
        float2 k01 = __bfloat1622float2(*(__nv_bfloat162*)&ku.x);
        float2 k23 = __bfloat1622float2(*(__nv_bfloat162*)&ku.y);
        float2 w01 = __bfloat1622float2(*(__nv_bfloat162*)&vu.x);
        float2 w23 = __bfloat1622float2(*(__nv_bfloat162*)&vu.y);
        v4 = make_float4(w01.x, w01.y, w23.x, w23.y);
        const float* ar = &attr[eid * EDIM];
        if (LAYER == 1) {
            a0 = __ldg(&ar[j]); a1 = __ldg(&ar[8 + j]);
            a2 = (j < 6) ? __ldg(&ar[16 + j]) : 0.f;
            t = q4.x * k01.x + q4.y * k01.y + q4.z * k23.x + q4.w * k23.y
              + a0 * qp0 + a1 * qp1 + a2 * qp2;
        } else {
            a0 = __ldg(&ar[j]);
            a1 = (j < 6) ? __ldg(&ar[16 + j]) : 0.f;
            a2 = 0.f;
            t = q4.x * k01.x + q4.y * k01.y + q4.z * k23.x + q4.w * k23.y
              + a0 * qp0 + a1 * qp1;
        }
#pragma unroll
        for (int o = LPH / 2; o; o >>= 1)
            t += __shfl_xor_sync(0xffffffffu, t, o);
        t *= scale;
    };

    int i = 0;
    for (; i + 4 <= deg; i += 4) {
        float t0, t1, t2, t3;
        float4 v0, v1, v2, v3;
        float a00, a01, a02, a10, a11, a12, a20, a21, a22, a30, a31, a32;
        body(e0 + i,     t0, v0, a00, a01, a02);
        body(e0 + i + 1, t1, v1, a10, a11, a12);
        body(e0 + i + 2, t2, v2, a20, a21, a22);
        body(e0 + i + 3, t3, v3, a30, a31, a32);
        float nm = fmaxf(fmaxf(m, fmaxf(t0, t1)), fmaxf(t2, t3));
        float c  = __expf(m - nm);
        float p0 = __expf(t0 - nm);
        float p1 = __expf(t1 - nm);
        float p2 = __expf(t2 - nm);
        float p3 = __expf(t3 - nm);
        s = s * c + p0 + p1 + p2 + p3;
        acc.x = acc.x * c + p0 * v0.x + p1 * v1.x + p2 * v2.x + p3 * v3.x;
        acc.y = acc.y * c + p0 * v0.y + p1 * v1.y + p2 * v2.y + p3 * v3.y;
        acc.z = acc.z * c + p0 * v0.z + p1 * v1.z + p2 * v2.z + p3 * v3.z;
        acc.w = acc.w * c + p0 * v0.w + p1 * v1.w + p2 * v2.w + p3 * v3.w;
        aa0 = aa0 * c + p0 * a00 + p1 * a10 + p2 * a20 + p3 * a30;
        aa1 = aa1 * c + p0 * a01 + p1 * a11 + p2 * a21 + p3 * a31;
        if (LAYER == 1) aa2 = aa2 * c + p0 * a02 + p1 * a12 + p2 * a22 + p3 * a32;
        m = nm;
    }
    for (; i < deg; i++) {
        float t0;
        float4 v0;
        float a00, a01, a02;
        body(e0 + i, t0, v0, a00, a01, a02);
        float nm = fmaxf(m, t0);
        float c  = __expf(m - nm);
        float p0 = __expf(t0 - nm);
        s = s * c + p0;
        acc.x = acc.x * c + p0 * v0.x;
        acc.y = acc.y * c + p0 * v0.y;
        acc.z = acc.z * c + p0 * v0.z;
        acc.w = acc.w * c + p0 * v0.w;
        aa0 = aa0 * c + p0 * a00;
        aa1 = aa1 * c + p0 * a01;
        if (LAYER == 1) aa2 = aa2 * c + p0 * a02;
        m = nm;
    }

    float inv = 1.f / (s + 1e-16f);
    acc.x *= inv; acc.y *= inv; acc.z *= inv; acc.w *= inv;
    aa0 *= inv; aa1 *= inv; aa2 *= inv;

    // attr-message: out_h += (sum_e alpha_eh * attr_e) @ We_h
    float4 ex = make_float4(0.f, 0.f, 0.f, 0.f);
#pragma unroll
    for (int g = 0; g < 22; g++) {
        float aag;
        if (g < LPH)            aag = __shfl_sync(0xffffffffu, aa0, gb + g);
        else if (g < 2 * LPH)   aag = __shfl_sync(0xffffffffu, aa1, gb + g - LPH);
        else                    aag = __shfl_sync(0xffffffffu, aa2, gb + g - 2 * LPH);
        float4 w4 = __ldg((const float4*)&we[g * D + cbase + 4 * l]);
        ex.x += aag * w4.x; ex.y += aag * w4.y;
        ex.z += aag * w4.z; ex.w += aag * w4.w;
    }

    float4 sk = *(const float4*)&drow[OS + cbase + 4 * l];
    float4 o;
    o.x = fmaxf(sk.x + acc.x + ex.x, 0.f);
    o.y = fmaxf(sk.y + acc.y + ex.y, 0.f);
    o.z = fmaxf(sk.z + acc.z + ex.z, 0.f);
    o.w = fmaxf(sk.w + acc.w + ex.w, 0.f);

    if (LAYER == 1) {
        __nv_bfloat16 hh[4];
        hh[0] = __float2bfloat16_rn(o.x);
        hh[1] = __float2bfloat16_rn(o.y);
        hh[2] = __float2bfloat16_rn(o.z);
        hh[3] = __float2bfloat16_rn(o.w);
        *(uint2*)&g_x1h[dst * D1 + cbase + 4 * l] = *(uint2*)hh;
    } else {
        // fused output head: sigmoid([x1 | x2] @ w_out + b)
        int c2 = cbase + 4 * l;
        float4 w4 = __ldg((const float4*)&wout[D1 + c2]);
        float part = o.x * w4.x + o.y * w4.y + o.z * w4.z + o.w * w4.w;
        int c1 = threadIdx.x * 2;
        __nv_bfloat162 x1h = *(const __nv_bfloat162*)&g_x1h[dst * D1 + c1];
        float2 x1v = __bfloat1622float2(x1h);
        float2 w1v = __ldg((const float2*)&wout[c1]);
        part += x1v.x * w1v.x + x1v.y * w1v.y;
#pragma unroll
        for (int of = 16; of; of >>= 1)
            part += __shfl_xor_sync(0xffffffffu, part, of);
        __shared__ float wsum[4];
        if (l == 0) wsum[w] = part;
        __syncthreads();
        if (threadIdx.x == 0) {
            float sfull = wsum[0] + wsum[1] + wsum[2] + wsum[3] + bout[0];
            out[dst] = 1.f / (1.f + expf(-sfull));
        }
    }
}

// ---------------- launch (forked-stream capture for DAG overlap) -------------
extern "C" void kernel_launch(void* const* d_in, const int* in_sizes, int n_in,
                              void* d_out, int out_size) {
    const float* x  = (const float*)d_in[0];
    const int*   ei = (const int*)d_in[1];
    const float* ea = (const float*)d_in[2];
    const float* w1_q = (const float*)d_in[3];  const float* b1_q = (const float*)d_in[4];
    const float* w1_k = (const float*)d_in[5];  const float* b1_k = (const float*)d_in[6];
    const float* w1_v = (const float*)d_in[7];  const float* b1_v = (const float*)d_in[8];
    const float* w1_e = (const float*)d_in[9];
    const float* w1_s = (const float*)d_in[10]; const float* b1_s = (const float*)d_in[11];
    const float* w2_q = (const float*)d_in[12]; const float* b2_q = (const float*)d_in[13];
    const float* w2_k = (const float*)d_in[14]; const float* b2_k = (const float*)d_in[15];
    const float* w2_v = (const float*)d_in[16]; const float* b2_v = (const float*)d_in[17];
    const float* w2_e = (const float*)d_in[18];
    const float* w2_s = (const float*)d_in[19]; const float* b2_s = (const float*)d_in[20];
    const float* w_out = (const float*)d_in[21];
    const float* b_out = (const float*)d_in[22];
    float* out = (float*)d_out;

    static int inited = 0;
    static cudaStream_t sA, sB;
    static cudaEvent_t evRoot, evA, evB;
    if (!inited) {
        cudaFuncSetAttribute(k_gemm2_tc,
                             cudaFuncAttributeMaxDynamicSharedMemorySize, G2_SMEM);
        cudaStreamCreateWithFlags(&sA, cudaStreamNonBlocking);
        cudaStreamCreateWithFlags(&sB, cudaStreamNonBlocking);
        cudaEventCreateWithFlags(&evRoot, cudaEventDisableTiming);
        cudaEventCreateWithFlags(&evA, cudaEventDisableTiming);
        cudaEventCreateWithFlags(&evB, cudaEventDisableTiming);
        inited = 1;
    }

    // fork side streams off the capture-origin stream
    cudaEventRecord(evRoot, 0);
    cudaStreamWaitEvent(sA, evRoot, 0);
    cudaStreamWaitEvent(sB, evRoot, 0);

    // stream A: CSR build chain (independent of GEMMs)
    k_detect<<<1, 32, 0, sA>>>(ei);
    k_zero_counters<<<(NN + 255) / 256, 256, 0, sA>>>();
    k_hist<<<(EE + 255) / 256, 256, 0, sA>>>(ei);
    k_scan1<<<SCB, 1024, 0, sA>>>();
    k_scan2<<<1, 64, 0, sA>>>();
    k_scan3<<<(NN + 255) / 256, 256, 0, sA>>>();
    k_scatter<<<(EE + 255) / 256, 256, 0, sA>>>(ei);
    cudaEventRecord(evA, sA);

    // stream B: layer2 weight fold (needed only by gemm2)
    k_wcat2<<<(D1 * W2COLS + W2COLS + 255) / 256, 256, 0, sB>>>(
        w2_q, b2_q, w2_k, b2_k, w2_v, b2_v, w2_e, w2_s, b2_s);
    cudaEventRecord(evB, sB);

    // main stream: layer1 projection
    k_wcat1<<<(FINN * W1COLS + W1COLS + 255) / 256, 256>>>(w1_q, b1_q, w1_k, b1_k,
                                                           w1_v, b1_v, w1_e, w1_s, b1_s);
    {
        dim3 g((NN + 127) / 128, (W1COLS + 127) / 128);
        k_gemm1<<<g, 256>>>(x);
    }
    cudaStreamWaitEvent(0, evA, 0);      // join CSR before edge pass
    k_edge<1><<<NN / 2, 128>>>(ea, w1_e, w_out, b_out, out);

    cudaStreamWaitEvent(0, evB, 0);      // join wcat2 before gemm2
    {
        dim3 g((NN + 127) / 128, W2COLS / 128);
        k_gemm2_tc<<<g, 256, G2_SMEM>>>();
    }
    k_edge<2><<<NN, 128>>>(ea, w2_e, w_out, b_out, out);
}